// round 12
// baseline (speedup 1.0000x reference)
#include <cuda_runtime.h>
#include <cuda_fp16.h>
#include <mma.h>

using namespace nvcuda;

#define VOCAB  32000
#define EMBED  512
#define HIDDEN 1024
#define BATCH  64
#define SEQ    512
#define DGATE  4096
#define NTOK   (BATCH * SEQ)

// ---------------- device scratch (static; no allocation) ----------------
__device__ __half  g_xh[(size_t)NTOK * EMBED];      // gathered embeddings fp16 (row = t*64+b)
__device__ __half  g_wx[(size_t)EMBED * DGATE];     // x-weights fp16, col = h*4+gate (f,i,c,o)
__device__ __half  g_wh[(size_t)HIDDEN * DGATE];    // h-weights fp16, same col layout
__device__ float   g_bias[DGATE];                   // interleaved biases
__device__ float   g_pre[(size_t)NTOK * DGATE];     // precomputed x-projections fp32
__device__ __half  g_wout[(size_t)HIDDEN * VOCAB];  // Wout fp16
__device__ __half  g_h[2][BATCH * HIDDEN];          // h double buffer fp16
__device__ unsigned g_cnt[2 * SEQ + 8];             // per-step producer counters [2t+group]

// ---------------- helpers ----------------
__device__ __forceinline__ void cp_async16(void* smem, const void* gmem) {
    unsigned s = (unsigned)__cvta_generic_to_shared(smem);
    asm volatile("cp.async.cg.shared.global [%0], [%1], 16;\n" :: "r"(s), "l"(gmem));
}
__device__ __forceinline__ void cp_commit() { asm volatile("cp.async.commit_group;\n"); }
template <int N> __device__ __forceinline__ void cp_wait() {
    asm volatile("cp.async.wait_group %0;\n" :: "n"(N));
}
__device__ __forceinline__ float sigf(float x)  { return 1.f / (1.f + __expf(-x)); }
__device__ __forceinline__ float tanhx(float x) { return 2.f * sigf(2.f * x) - 1.f; }

// m16n8k16 row.col f32.f16.f16.f32; C accumulates in place
__device__ __forceinline__ void mma16816(float c[4], const unsigned a[4], const unsigned b[2]) {
    asm("mma.sync.aligned.m16n8k16.row.col.f32.f16.f16.f32 "
        "{%0,%1,%2,%3}, {%4,%5,%6,%7}, {%8,%9}, {%0,%1,%2,%3};"
        : "+f"(c[0]), "+f"(c[1]), "+f"(c[2]), "+f"(c[3])
        : "r"(a[0]), "r"(a[1]), "r"(a[2]), "r"(a[3]), "r"(b[0]), "r"(b[1]));
}

// ldmatrix x4: loads a 16x16 half tile as 4 8x8 matrices (A-operand layout)
__device__ __forceinline__ void ldsm4(unsigned a[4], const __half* lane_base) {
    unsigned addr = (unsigned)__cvta_generic_to_shared(lane_base);
    asm volatile("ldmatrix.sync.aligned.m8n8.x4.shared.b16 {%0,%1,%2,%3}, [%4];"
        : "=r"(a[0]), "=r"(a[1]), "=r"(a[2]), "=r"(a[3]) : "r"(addr));
}

// ---------------- init: zero h buffers + producer counters ----------------
__global__ void k_init() {
    int i = blockIdx.x * blockDim.x + threadIdx.x;
    if (i < 2 * SEQ + 8) g_cnt[i] = (i < 2) ? 64u : 0u;   // h_0 ready at t=0
    __half* h = &g_h[0][0];
    const int n = 2 * BATCH * HIDDEN;
    for (; i < n; i += gridDim.x * blockDim.x) h[i] = __float2half(0.f);
}

// ---------------- weight conversion (gate interleave, fp16) ----------------
__global__ void k_convw(const float* __restrict__ Wf, const float* __restrict__ Wi,
                        const float* __restrict__ Wc, const float* __restrict__ Wo,
                        const float* __restrict__ bf, const float* __restrict__ bi,
                        const float* __restrict__ bc, const float* __restrict__ bo) {
    int i = blockIdx.x * blockDim.x + threadIdx.x;   // over 1536*1024
    if (i >= (EMBED + HIDDEN) * HIDDEN) return;
    int k = i >> 10, h = i & 1023;
    size_t src = (size_t)k * HIDDEN + h;
    __half2 lo = __floats2half2_rn(Wf[src], Wi[src]);
    __half2 hi = __floats2half2_rn(Wc[src], Wo[src]);
    __half2* dst;
    if (k < EMBED) dst = (__half2*)(g_wx + (size_t)k * DGATE + h * 4);
    else           dst = (__half2*)(g_wh + (size_t)(k - EMBED) * DGATE + h * 4);
    dst[0] = lo; dst[1] = hi;
    if (i < HIDDEN) {
        g_bias[i * 4 + 0] = bf[i]; g_bias[i * 4 + 1] = bi[i];
        g_bias[i * 4 + 2] = bc[i]; g_bias[i * 4 + 3] = bo[i];
    }
}

__global__ void k_convwout(const float* __restrict__ Wout) {
    size_t stride = (size_t)gridDim.x * blockDim.x;
    size_t npair = (size_t)HIDDEN * VOCAB / 2;
    for (size_t i = blockIdx.x * (size_t)blockDim.x + threadIdx.x; i < npair; i += stride) {
        float2 v = ((const float2*)Wout)[i];
        ((__half2*)g_wout)[i] = __floats2half2_rn(v.x, v.y);
    }
}

// ---------------- embedding gather (row = t*64 + b), 8 halfs/thread ----------------
__global__ void k_gather(const int* __restrict__ ids, const float* __restrict__ emb) {
    int i = blockIdx.x * blockDim.x + threadIdx.x;   // over NTOK * (EMBED/8)
    int r = i >> 6, seg = i & 63;
    int t = r >> 6, b = r & 63;
    int tok = ids[b * SEQ + t];
    const float4* s = (const float4*)(emb + (size_t)tok * EMBED + seg * 8);
    float4 v0 = s[0], v1 = s[1];
    __half2 h01 = __floats2half2_rn(v0.x, v0.y);
    __half2 h23 = __floats2half2_rn(v0.z, v0.w);
    __half2 h45 = __floats2half2_rn(v1.x, v1.y);
    __half2 h67 = __floats2half2_rn(v1.z, v1.w);
    uint4 pack;
    pack.x = *(unsigned*)&h01; pack.y = *(unsigned*)&h23;
    pack.z = *(unsigned*)&h45; pack.w = *(unsigned*)&h67;
    *(uint4*)(g_xh + (size_t)i * 8) = pack;
}

// ---------------- phase 1: Pre = Xh @ Wx  (M=32768, N=4096, K=512) ----------------
__global__ void __launch_bounds__(256, 1) k_gemm1() {
    extern __shared__ char smem[];
    __half* As = (__half*)smem;                              // [2][128][72]
    __half* Bs = (__half*)(smem + 2 * 128 * 72 * 2);         // [2][64][264]
    const int n0 = blockIdx.x * 256;
    const int m0 = blockIdx.y * 128;
    const int tid = threadIdx.x;
    const int w = tid >> 5;
    const int wm = w & 1, wn = w >> 1;

    wmma::fragment<wmma::accumulator, 16, 16, 16, float> acc[4][4];
#pragma unroll
    for (int i = 0; i < 4; i++)
#pragma unroll
        for (int j = 0; j < 4; j++) wmma::fill_fragment(acc[i][j], 0.f);

    auto loadAB = [&](int buf, int kc) {
        __half* a = As + buf * (128 * 72);
        __half* b = Bs + buf * (64 * 264);
        const __half* gA = g_xh + (size_t)m0 * EMBED + kc * 64;
        const __half* gB = g_wx + (size_t)(kc * 64) * DGATE + n0;
#pragma unroll
        for (int i = tid; i < 1024; i += 256) {
            int r = i >> 3, c = i & 7;
            cp_async16(a + r * 72 + c * 8, gA + (size_t)r * EMBED + c * 8);
        }
#pragma unroll
        for (int i = tid; i < 2048; i += 256) {
            int r = i >> 5, c = i & 31;
            cp_async16(b + r * 264 + c * 8, gB + (size_t)r * DGATE + c * 8);
        }
    };

    loadAB(0, 0);
    cp_commit();
    const int KC = EMBED / 64;   // 8
    for (int kc = 0; kc < KC; ++kc) {
        if (kc + 1 < KC) { loadAB((kc + 1) & 1, kc + 1); cp_commit(); cp_wait<1>(); }
        else             { cp_wait<0>(); }
        __syncthreads();
        const __half* a = As + (kc & 1) * (128 * 72) + wm * 64 * 72;
        const __half* b = Bs + (kc & 1) * (64 * 264) + wn * 64;
#pragma unroll
        for (int kk = 0; kk < 4; ++kk) {
            wmma::fragment<wmma::matrix_a, 16, 16, 16, __half, wmma::row_major> fa[4];
            wmma::fragment<wmma::matrix_b, 16, 16, 16, __half, wmma::row_major> fb[4];
#pragma unroll
            for (int i = 0; i < 4; i++) wmma::load_matrix_sync(fa[i], a + i * 16 * 72 + kk * 16, 72);
#pragma unroll
            for (int j = 0; j < 4; j++) wmma::load_matrix_sync(fb[j], b + kk * 16 * 264 + j * 16, 264);
#pragma unroll
            for (int i = 0; i < 4; i++)
#pragma unroll
                for (int j = 0; j < 4; j++) wmma::mma_sync(acc[i][j], fa[i], fb[j], acc[i][j]);
        }
        __syncthreads();
    }
#pragma unroll
    for (int i = 0; i < 4; i++)
#pragma unroll
        for (int j = 0; j < 4; j++) {
            float* dst = g_pre + (size_t)(m0 + wm * 64 + i * 16) * DGATE + n0 + wn * 64 + j * 16;
            wmma::store_matrix_sync(dst, acc[i][j], DGATE, wmma::mem_row_major);
        }
}

// ---------------- persistent recurrence: producer-count dataflow ----------------
// 128 CTAs; CTA owns gate cols [cta*32, +32) = hidden units [cta*8, +8).
// NO global barrier. Chunk kc of h (512 cols) depends only on producer CTAs
// [kc*64, kc*64+64); each chunk gated by a per-step counter reaching 64.
// Passing both gates at step t also proves all CTAs finished step t-1, which
// is exactly the WAR condition for writing buffer (t+1)&1. Chunk-1 stragglers
// hide under chunk-0 load+MMA. Reg-resident Wh; ldsm4 A-frags; proven epilogue.
__global__ void __launch_bounds__(256, 1) k_rnn() {
    extern __shared__ char smem[];
    __half* hs   = (__half*)smem;                          // [2][64][520] 133120 B
    float*  part = (float*)(smem + 133120);                // [8][64][36]  73728 B
    float*  bias = (float*)(smem + 133120 + 73728);        // [32]
    const int cta  = blockIdx.x;
    const int n0   = cta * 32;
    const int tid  = threadIdx.x;
    const int w    = tid >> 5;
    const int lane = tid & 31;
    const int g    = lane >> 2;   // groupID
    const int tg   = lane & 3;    // thread-in-group
    const int my_group = cta >> 6; // which chunk this CTA's h-slice feeds

    if (tid < 32) bias[tid] = g_bias[n0 + tid];

    // one-time register B fragments (proven lane mapping):
    // warp w, chunk kc, sub kk2 -> k base = kc*512 + w*64 + kk2*16
    unsigned bfrag[2][4][4][2];
#pragma unroll
    for (int kc = 0; kc < 2; kc++)
#pragma unroll
        for (int kk2 = 0; kk2 < 4; kk2++)
#pragma unroll
            for (int nt = 0; nt < 4; nt++) {
                const int kb = kc * 512 + w * 64 + kk2 * 16;
                const int n  = n0 + nt * 8 + g;
                __half x0 = g_wh[(size_t)(kb + tg * 2    ) * DGATE + n];
                __half x1 = g_wh[(size_t)(kb + tg * 2 + 1) * DGATE + n];
                __half x2 = g_wh[(size_t)(kb + tg * 2 + 8) * DGATE + n];
                __half x3 = g_wh[(size_t)(kb + tg * 2 + 9) * DGATE + n];
                __half2 p0 = __halves2half2(x0, x1);
                __half2 p1 = __halves2half2(x2, x3);
                bfrag[kc][kk2][nt][0] = *(unsigned*)&p0;
                bfrag[kc][kk2][nt][1] = *(unsigned*)&p1;
            }
    __syncthreads();

    float cst0 = 0.f, cst1 = 0.f;
    const int b0 = tid >> 3, hu0 = tid & 7;
    const int b1 = (tid + 256) >> 3, hu1 = tid & 7;
    // ldmatrix per-lane row/col offset within a 16x16 A tile
    const int lrow = lane & 15, lcol = (lane >> 4) * 8;

#pragma unroll 1
    for (int t = 0; t < SEQ; ++t) {
        const __half* hsrc = g_h[t & 1];
        __half*       hdst = g_h[(t + 1) & 1];

        // prefetch gate pre-activations (independent DRAM stream)
        const float* pret = g_pre + (size_t)t * BATCH * DGATE;
        float4 pr0 = __ldg((const float4*)(pret + (size_t)b0 * DGATE + n0 + hu0 * 4));
        float4 pr1 = __ldg((const float4*)(pret + (size_t)b1 * DGATE + n0 + hu1 * 4));

        float acc[4][4][4];
#pragma unroll
        for (int mt = 0; mt < 4; mt++)
#pragma unroll
            for (int nt = 0; nt < 4; nt++)
#pragma unroll
                for (int q = 0; q < 4; q++) acc[mt][nt][q] = 0.f;

        // ---- gate chunk 0 (producers 0..63), then issue its cp.async ----
        if (tid == 0) {
            while (((volatile unsigned*)g_cnt)[2 * t] < 64u) { }
            __threadfence();
        }
        __syncthreads();
        {
            __half* dst = hs;
            const __half* src = hsrc;
#pragma unroll
            for (int i = tid; i < 4096; i += 256) {
                int r = i >> 6, c = i & 63;
                cp_async16(dst + r * 520 + c * 8, src + (size_t)r * HIDDEN + c * 8);
            }
            cp_commit();
        }

        // ---- gate chunk 1 (producers 64..127), issue while chunk 0 flies ----
        if (tid == 0) {
            while (((volatile unsigned*)g_cnt)[2 * t + 1] < 64u) { }
            __threadfence();
        }
        __syncthreads();
        {
            __half* dst = hs + 64 * 520;
            const __half* src = hsrc + 512;
#pragma unroll
            for (int i = tid; i < 4096; i += 256) {
                int r = i >> 6, c = i & 63;
                cp_async16(dst + r * 520 + c * 8, src + (size_t)r * HIDDEN + c * 8);
            }
            cp_commit();
        }

#pragma unroll
        for (int kc = 0; kc < 2; ++kc) {
            if (kc == 0) cp_wait<1>();
            else         cp_wait<0>();
            __syncthreads();
            const __half* hb = hs + kc * (64 * 520);
#pragma unroll
            for (int kk2 = 0; kk2 < 4; ++kk2) {
                const int colb = w * 64 + kk2 * 16;
                unsigned a[4][4];
#pragma unroll
                for (int mt = 0; mt < 4; mt++)
                    ldsm4(a[mt], hb + (size_t)(mt * 16 + lrow) * 520 + colb + lcol);
#pragma unroll
                for (int mt = 0; mt < 4; mt++)
#pragma unroll
                    for (int nt = 0; nt < 4; nt++)
                        mma16816(acc[mt][nt], a[mt], bfrag[kc][kk2][nt]);
            }
        }

        // partial store: warp-exclusive padded region
        float* pw = part + w * 2304;
#pragma unroll
        for (int mt = 0; mt < 4; mt++)
#pragma unroll
            for (int nt = 0; nt < 4; nt++) {
                const int r = mt * 16 + g, c = nt * 8 + tg * 2;
                *(float2*)&pw[r * 36 + c]       = make_float2(acc[mt][nt][0], acc[mt][nt][1]);
                *(float2*)&pw[(r + 8) * 36 + c] = make_float2(acc[mt][nt][2], acc[mt][nt][3]);
            }
        __syncthreads();

        // fused reduce + gates + state update (pairs tid and tid+256)
        {
            float4 bb = *(const float4*)(bias + hu0 * 4);
            float xf = pr0.x + bb.x, xi = pr0.y + bb.y, xg = pr0.z + bb.z, xo = pr0.w + bb.w;
#pragma unroll
            for (int ww = 0; ww < 8; ++ww) {
                float4 q = *(const float4*)(part + ww * 2304 + b0 * 36 + hu0 * 4);
                xf += q.x; xi += q.y; xg += q.z; xo += q.w;
            }
            float f = sigf(xf), ii = sigf(xi), gg = tanhx(xg), o = sigf(xo);
            cst0 = cst0 * f + gg * ii;
            hdst[b0 * HIDDEN + cta * 8 + hu0] = __float2half(cst0 * o);
        }
        {
            float4 bb = *(const float4*)(bias + hu1 * 4);
            float xf = pr1.x + bb.x, xi = pr1.y + bb.y, xg = pr1.z + bb.z, xo = pr1.w + bb.w;
#pragma unroll
            for (int ww = 0; ww < 8; ++ww) {
                float4 q = *(const float4*)(part + ww * 2304 + b1 * 36 + hu1 * 4);
                xf += q.x; xi += q.y; xg += q.z; xo += q.w;
            }
            float f = sigf(xf), ii = sigf(xi), gg = tanhx(xg), o = sigf(xo);
            cst1 = cst1 * f + gg * ii;
            hdst[b1 * HIDDEN + cta * 8 + hu1] = __float2half(cst1 * o);
        }

        // producer arrival: h_{t+1} slice visible -> bump this step's counter
        __threadfence();
        __syncthreads();
        if (tid == 0) atomicAdd(&g_cnt[2 * (t + 1) + my_group], 1u);
    }
}

// ---------------- readout: logits = h_final @ Wout + bout ----------------
__global__ void __launch_bounds__(256, 1) k_readout(const float* __restrict__ bout,
                                                    float* __restrict__ out) {
    extern __shared__ char smem[];
    __half* hsm   = (__half*)smem;                  // [64][1032]  132096 B
    float*  stage = (float*)(smem + 132096);        // [64][132]   33792 B
    const int n0 = blockIdx.x * 128;
    const int tid = threadIdx.x;
    const int w = tid >> 5;
    const __half* hfin = g_h[0];   // final h after SEQ=512 steps

    for (int i = tid; i < 64 * 128; i += 256) {
        int r = i >> 7, c = i & 127;
        *(float4*)(hsm + r * 1032 + c * 8) = *(const float4*)(hfin + (size_t)r * HIDDEN + c * 8);
    }
    __syncthreads();

    wmma::fragment<wmma::accumulator, 16, 16, 16, float> acc[4];
#pragma unroll
    for (int i = 0; i < 4; i++) wmma::fill_fragment(acc[i], 0.f);

#pragma unroll 1
    for (int kk = 0; kk < 64; ++kk) {
        wmma::fragment<wmma::matrix_a, 16, 16, 16, __half, wmma::row_major> fa;
        wmma::fragment<wmma::matrix_b, 16, 16, 16, __half, wmma::row_major> fb;
        wmma::load_matrix_sync(fb, g_wout + (size_t)(kk * 16) * VOCAB + n0 + w * 16, VOCAB);
#pragma unroll
        for (int i = 0; i < 4; i++) {
            wmma::load_matrix_sync(fa, hsm + i * 16 * 1032 + kk * 16, 1032);
            wmma::mma_sync(acc[i], fa, fb, acc[i]);
        }
    }
#pragma unroll
    for (int i = 0; i < 4; i++)
        wmma::store_matrix_sync(stage + i * 16 * 132 + w * 16, acc[i], 132, wmma::mem_row_major);
    __syncthreads();

    for (int i = tid; i < 64 * 128; i += 256) {
        int r = i >> 7, c = i & 127;
        out[(size_t)r * VOCAB + n0 + c] = stage[r * 132 + c] + bout[n0 + c];
    }
}

// ---------------- launch ----------------
extern "C" void kernel_launch(void* const* d_in, const int* in_sizes, int n_in,
                              void* d_out, int out_size) {
    const int*   ids  = (const int*)d_in[0];
    const float* emb  = (const float*)d_in[1];
    const float* Wf   = (const float*)d_in[2];
    const float* bf   = (const float*)d_in[3];
    const float* Wi   = (const float*)d_in[4];
    const float* bi   = (const float*)d_in[5];
    const float* Wc   = (const float*)d_in[6];
    const float* bc   = (const float*)d_in[7];
    const float* Wo   = (const float*)d_in[8];
    const float* bo   = (const float*)d_in[9];
    const float* Wout = (const float*)d_in[10];
    const float* bout = (const float*)d_in[11];
    float* out = (float*)d_out;

    const int smem1 = 2 * 128 * 72 * 2 + 2 * 64 * 264 * 2;            // 104448
    const int smemR = 133120 + 73728 + 128;                           // 206976
    const int smemO = 64 * 1032 * 2 + 64 * 132 * 4;                   // 165888
    cudaFuncSetAttribute(k_gemm1,   cudaFuncAttributeMaxDynamicSharedMemorySize, smem1);
    cudaFuncSetAttribute(k_rnn,     cudaFuncAttributeMaxDynamicSharedMemorySize, smemR);
    cudaFuncSetAttribute(k_readout, cudaFuncAttributeMaxDynamicSharedMemorySize, smemO);

    k_init<<<256, 256>>>();
    k_convw<<<(1536 * 1024 + 255) / 256, 256>>>(Wf, Wi, Wc, Wo, bf, bi, bc, bo);
    k_convwout<<<8192, 256>>>(Wout);
    k_gather<<<NTOK * (EMBED / 8) / 256, 256>>>(ids, emb);
    k_gemm1<<<dim3(DGATE / 256, NTOK / 128), 256, smem1>>>();
    k_rnn<<<128, 256, smemR>>>();
    k_readout<<<VOCAB / 128, 256, smemO>>>(bout, out);
}

// round 13
// speedup vs baseline: 1.1725x; 1.1725x over previous
#include <cuda_runtime.h>
#include <cuda_fp16.h>
#include <mma.h>

using namespace nvcuda;

#define VOCAB  32000
#define EMBED  512
#define HIDDEN 1024
#define BATCH  64
#define SEQ    512
#define DGATE  4096
#define NTOK   (BATCH * SEQ)

// ---------------- device scratch (static; no allocation) ----------------
__device__ __half  g_xh[(size_t)NTOK * EMBED];      // gathered embeddings fp16 (row = t*64+b)
__device__ __half  g_wx[(size_t)EMBED * DGATE];     // x-weights fp16, col = h*4+gate (f,i,c,o)
__device__ __half  g_wh[(size_t)HIDDEN * DGATE];    // h-weights fp16, same col layout
__device__ float   g_bias[DGATE];                   // interleaved biases
__device__ __half  g_pre[(size_t)NTOK * DGATE];     // precomputed x-projections fp16
__device__ __half  g_wout[(size_t)HIDDEN * VOCAB];  // Wout fp16
__device__ __half  g_h[2][BATCH * HIDDEN];          // h double buffer fp16
__device__ unsigned g_bar;                          // grid barrier counter

// ---------------- helpers ----------------
__device__ __forceinline__ void cp_async16(void* smem, const void* gmem) {
    unsigned s = (unsigned)__cvta_generic_to_shared(smem);
    asm volatile("cp.async.cg.shared.global [%0], [%1], 16;\n" :: "r"(s), "l"(gmem));
}
__device__ __forceinline__ void cp_commit() { asm volatile("cp.async.commit_group;\n"); }
template <int N> __device__ __forceinline__ void cp_wait() {
    asm volatile("cp.async.wait_group %0;\n" :: "n"(N));
}
__device__ __forceinline__ float sigf(float x)  { return 1.f / (1.f + __expf(-x)); }
__device__ __forceinline__ float tanhx(float x) { return 2.f * sigf(2.f * x) - 1.f; }

// load 4 consecutive halfs (8B) and widen to float4
__device__ __forceinline__ float4 ldg_half4(const __half* p) {
    uint2 v = __ldg((const uint2*)p);
    __half2 h0 = *(__half2*)&v.x, h1 = *(__half2*)&v.y;
    float2 f0 = __half22float2(h0), f1 = __half22float2(h1);
    return make_float4(f0.x, f0.y, f1.x, f1.y);
}

// m16n8k16 row.col f32.f16.f16.f32; C accumulates in place
__device__ __forceinline__ void mma16816(float c[4], const unsigned a[4], const unsigned b[2]) {
    asm("mma.sync.aligned.m16n8k16.row.col.f32.f16.f16.f32 "
        "{%0,%1,%2,%3}, {%4,%5,%6,%7}, {%8,%9}, {%0,%1,%2,%3};"
        : "+f"(c[0]), "+f"(c[1]), "+f"(c[2]), "+f"(c[3])
        : "r"(a[0]), "r"(a[1]), "r"(a[2]), "r"(a[3]), "r"(b[0]), "r"(b[1]));
}

// ldmatrix x4: loads a 16x16 half tile as 4 8x8 matrices (A-operand layout)
__device__ __forceinline__ void ldsm4(unsigned a[4], const __half* lane_base) {
    unsigned addr = (unsigned)__cvta_generic_to_shared(lane_base);
    asm volatile("ldmatrix.sync.aligned.m8n8.x4.shared.b16 {%0,%1,%2,%3}, [%4];"
        : "=r"(a[0]), "=r"(a[1]), "=r"(a[2]), "=r"(a[3]) : "r"(addr));
}

// ---------------- init: zero h buffers + barrier ----------------
__global__ void k_init() {
    int i = blockIdx.x * blockDim.x + threadIdx.x;
    if (i == 0) g_bar = 0;
    __half* h = &g_h[0][0];
    const int n = 2 * BATCH * HIDDEN;
    for (; i < n; i += gridDim.x * blockDim.x) h[i] = __float2half(0.f);
}

// ---------------- weight conversion (gate interleave, fp16) ----------------
__global__ void k_convw(const float* __restrict__ Wf, const float* __restrict__ Wi,
                        const float* __restrict__ Wc, const float* __restrict__ Wo,
                        const float* __restrict__ bf, const float* __restrict__ bi,
                        const float* __restrict__ bc, const float* __restrict__ bo) {
    int i = blockIdx.x * blockDim.x + threadIdx.x;   // over 1536*1024
    if (i >= (EMBED + HIDDEN) * HIDDEN) return;
    int k = i >> 10, h = i & 1023;
    size_t src = (size_t)k * HIDDEN + h;
    __half2 lo = __floats2half2_rn(Wf[src], Wi[src]);
    __half2 hi = __floats2half2_rn(Wc[src], Wo[src]);
    __half2* dst;
    if (k < EMBED) dst = (__half2*)(g_wx + (size_t)k * DGATE + h * 4);
    else           dst = (__half2*)(g_wh + (size_t)(k - EMBED) * DGATE + h * 4);
    dst[0] = lo; dst[1] = hi;
    if (i < HIDDEN) {
        g_bias[i * 4 + 0] = bf[i]; g_bias[i * 4 + 1] = bi[i];
        g_bias[i * 4 + 2] = bc[i]; g_bias[i * 4 + 3] = bo[i];
    }
}

__global__ void k_convwout(const float* __restrict__ Wout) {
    size_t stride = (size_t)gridDim.x * blockDim.x;
    size_t npair = (size_t)HIDDEN * VOCAB / 2;
    for (size_t i = blockIdx.x * (size_t)blockDim.x + threadIdx.x; i < npair; i += stride) {
        float2 v = ((const float2*)Wout)[i];
        ((__half2*)g_wout)[i] = __floats2half2_rn(v.x, v.y);
    }
}

// ---------------- embedding gather (row = t*64 + b), 8 halfs/thread ----------------
__global__ void k_gather(const int* __restrict__ ids, const float* __restrict__ emb) {
    int i = blockIdx.x * blockDim.x + threadIdx.x;   // over NTOK * (EMBED/8)
    int r = i >> 6, seg = i & 63;
    int t = r >> 6, b = r & 63;
    int tok = ids[b * SEQ + t];
    const float4* s = (const float4*)(emb + (size_t)tok * EMBED + seg * 8);
    float4 v0 = s[0], v1 = s[1];
    __half2 h01 = __floats2half2_rn(v0.x, v0.y);
    __half2 h23 = __floats2half2_rn(v0.z, v0.w);
    __half2 h45 = __floats2half2_rn(v1.x, v1.y);
    __half2 h67 = __floats2half2_rn(v1.z, v1.w);
    uint4 pack;
    pack.x = *(unsigned*)&h01; pack.y = *(unsigned*)&h23;
    pack.z = *(unsigned*)&h45; pack.w = *(unsigned*)&h67;
    *(uint4*)(g_xh + (size_t)i * 8) = pack;
}

// ---------------- phase 1: Pre = Xh @ Wx  (M=32768, N=4096, K=512) ----------------
// CTA tile 128x128, 2 CTAs/SM, fp16 output staged through freed smem.
__global__ void __launch_bounds__(256, 2) k_gemm1() {
    extern __shared__ char smem[];
    __half* As = (__half*)smem;                       // [2][128][72] 36864 B
    __half* Bs = (__half*)(smem + 36864);             // [2][64][136] 34816 B
    float*  stage = (float*)smem;                     // [128][132]   67584 B (aliases A+B post-MMA)
    const int n0 = blockIdx.x * 128;
    const int m0 = blockIdx.y * 128;
    const int tid = threadIdx.x;
    const int w = tid >> 5;
    const int wm = w & 1, wn = w >> 1;   // 2m x 4n warps; warp tile 64x32

    wmma::fragment<wmma::accumulator, 16, 16, 16, float> acc[4][2];
#pragma unroll
    for (int i = 0; i < 4; i++) {
        wmma::fill_fragment(acc[i][0], 0.f);
        wmma::fill_fragment(acc[i][1], 0.f);
    }

    auto loadAB = [&](int buf, int kc) {
        __half* a = As + buf * (128 * 72);
        __half* b = Bs + buf * (64 * 136);
        const __half* gA = g_xh + (size_t)m0 * EMBED + kc * 64;
        const __half* gB = g_wx + (size_t)(kc * 64) * DGATE + n0;
#pragma unroll
        for (int i = tid; i < 1024; i += 256) {
            int r = i >> 3, c = i & 7;
            cp_async16(a + r * 72 + c * 8, gA + (size_t)r * EMBED + c * 8);
        }
#pragma unroll
        for (int i = tid; i < 1024; i += 256) {
            int r = i >> 4, c = i & 15;
            cp_async16(b + r * 136 + c * 8, gB + (size_t)r * DGATE + c * 8);
        }
    };

    loadAB(0, 0);
    cp_commit();
    const int KC = EMBED / 64;   // 8
    for (int kc = 0; kc < KC; ++kc) {
        if (kc + 1 < KC) { loadAB((kc + 1) & 1, kc + 1); cp_commit(); cp_wait<1>(); }
        else             { cp_wait<0>(); }
        __syncthreads();
        const __half* a = As + (kc & 1) * (128 * 72) + wm * 64 * 72;
        const __half* b = Bs + (kc & 1) * (64 * 136) + wn * 32;
#pragma unroll
        for (int kk = 0; kk < 4; ++kk) {
            wmma::fragment<wmma::matrix_b, 16, 16, 16, __half, wmma::row_major> fb[2];
#pragma unroll
            for (int j = 0; j < 2; j++) wmma::load_matrix_sync(fb[j], b + kk * 16 * 136 + j * 16, 136);
#pragma unroll
            for (int i = 0; i < 4; i++) {
                wmma::fragment<wmma::matrix_a, 16, 16, 16, __half, wmma::row_major> fa;
                wmma::load_matrix_sync(fa, a + i * 16 * 72 + kk * 16, 72);
                wmma::mma_sync(acc[i][0], fa, fb[0], acc[i][0]);
                wmma::mma_sync(acc[i][1], fa, fb[1], acc[i][1]);
            }
        }
        __syncthreads();
    }

    // epilogue: stage fp32 in smem (aliases A/B), convert to fp16, vector store
#pragma unroll
    for (int i = 0; i < 4; i++)
#pragma unroll
        for (int j = 0; j < 2; j++)
            wmma::store_matrix_sync(stage + (wm * 64 + i * 16) * 132 + wn * 32 + j * 16,
                                    acc[i][j], 132, wmma::mem_row_major);
    __syncthreads();
#pragma unroll
    for (int i = tid; i < 2048; i += 256) {
        int r = i >> 4, c8 = (i & 15) * 8;
        const float* s = stage + r * 132 + c8;
        __half2 p0 = __floats2half2_rn(s[0], s[1]);
        __half2 p1 = __floats2half2_rn(s[2], s[3]);
        __half2 p2 = __floats2half2_rn(s[4], s[5]);
        __half2 p3 = __floats2half2_rn(s[6], s[7]);
        uint4 pack;
        pack.x = *(unsigned*)&p0; pack.y = *(unsigned*)&p1;
        pack.z = *(unsigned*)&p2; pack.w = *(unsigned*)&p3;
        *(uint4*)(g_pre + (size_t)(m0 + r) * DGATE + n0 + c8) = pack;
    }
}

// ---------------- persistent recurrence: reg weights + 3-buf cp.async (R10 proven) ----------------
// 128 CTAs; CTA owns gate cols [cta*32, +32) = hidden units [cta*8, +8).
// Per step: h staged in 3-buffer cp.async pipeline (2-chunk lookahead, ONE sync
// per chunk); warp w covers k-local [w*32,+32) of each 256-col chunk; A-frags
// via ldmatrix.x4; Wh B-frags register-resident (built once); partials to
// dedicated smem; fused epilogue; proven atomic grid barrier. 7 syncs/step.
__global__ void __launch_bounds__(256, 1) k_rnn() {
    extern __shared__ char smem[];
    __half* hs   = (__half*)smem;                          // [3][64][264] 101376 B
    float*  part = (float*)(smem + 101376);                // [8][64][36]  73728 B
    float*  bias = (float*)(smem + 101376 + 73728);        // [32]
    const int cta  = blockIdx.x;
    const int n0   = cta * 32;
    const int tid  = threadIdx.x;
    const int w    = tid >> 5;
    const int lane = tid & 31;
    const int g    = lane >> 2;   // groupID
    const int tg   = lane & 3;    // thread-in-group

    if (tid < 32) bias[tid] = g_bias[n0 + tid];

    // one-time register B fragments (proven lane mapping):
    // warp w, chunk kc, sub kk2 -> k base = kc*256 + w*32 + kk2*16
    unsigned bfrag[4][2][4][2];
#pragma unroll
    for (int kc = 0; kc < 4; kc++)
#pragma unroll
        for (int kk2 = 0; kk2 < 2; kk2++)
#pragma unroll
            for (int nt = 0; nt < 4; nt++) {
                const int kb = kc * 256 + w * 32 + kk2 * 16;
                const int n  = n0 + nt * 8 + g;
                __half x0 = g_wh[(size_t)(kb + tg * 2    ) * DGATE + n];
                __half x1 = g_wh[(size_t)(kb + tg * 2 + 1) * DGATE + n];
                __half x2 = g_wh[(size_t)(kb + tg * 2 + 8) * DGATE + n];
                __half x3 = g_wh[(size_t)(kb + tg * 2 + 9) * DGATE + n];
                __half2 p0 = __halves2half2(x0, x1);
                __half2 p1 = __halves2half2(x2, x3);
                bfrag[kc][kk2][nt][0] = *(unsigned*)&p0;
                bfrag[kc][kk2][nt][1] = *(unsigned*)&p1;
            }
    __syncthreads();

    float cst0 = 0.f, cst1 = 0.f;
    const int b0 = tid >> 3, hu0 = tid & 7;
    const int b1 = (tid + 256) >> 3, hu1 = tid & 7;
    // ldmatrix per-lane row/col offset within a 16x16 A tile
    const int lrow = lane & 15, lcol = (lane >> 4) * 8;

#pragma unroll 1
    for (int t = 0; t < SEQ; ++t) {
        const __half* hsrc = g_h[t & 1];
        __half*       hdst = g_h[(t + 1) & 1];

        // prefetch gate pre-activations (fp16, independent DRAM stream)
        const __half* pret = g_pre + (size_t)t * BATCH * DGATE;
        float4 pr0 = ldg_half4(pret + (size_t)b0 * DGATE + n0 + hu0 * 4);
        float4 pr1 = ldg_half4(pret + (size_t)b1 * DGATE + n0 + hu1 * 4);

        float acc[4][4][4];
#pragma unroll
        for (int mt = 0; mt < 4; mt++)
#pragma unroll
            for (int nt = 0; nt < 4; nt++)
#pragma unroll
                for (int q = 0; q < 4; q++) acc[mt][nt][q] = 0.f;

        // issue chunks 0 and 1 (one commit group each)
#pragma unroll
        for (int c0 = 0; c0 < 2; ++c0) {
            __half* dst = hs + c0 * (64 * 264);
            const __half* src = hsrc + c0 * 256;
#pragma unroll
            for (int i = tid; i < 2048; i += 256) {
                int r = i >> 5, c = i & 31;
                cp_async16(dst + r * 264 + c * 8, src + (size_t)r * HIDDEN + c * 8);
            }
            cp_commit();
        }

#pragma unroll
        for (int kc = 0; kc < 4; ++kc) {
            if (kc < 3) cp_wait<1>();
            else        cp_wait<0>();
            __syncthreads();
            // issue chunk kc+2 into buffer (kc+2)%3 (safe: its consumer, MMA
            // of chunk kc-1, completed on all warps before the sync above)
            if (kc < 2) {
                __half* dst = hs + ((kc + 2) % 3) * (64 * 264);
                const __half* src = hsrc + (kc + 2) * 256;
#pragma unroll
                for (int i = tid; i < 2048; i += 256) {
                    int r = i >> 5, c = i & 31;
                    cp_async16(dst + r * 264 + c * 8, src + (size_t)r * HIDDEN + c * 8);
                }
                cp_commit();
            }
            const __half* hb = hs + (kc % 3) * (64 * 264);
#pragma unroll
            for (int kk2 = 0; kk2 < 2; ++kk2) {
                const int colb = w * 32 + kk2 * 16;
                unsigned a[4][4];
#pragma unroll
                for (int mt = 0; mt < 4; mt++)
                    ldsm4(a[mt], hb + (size_t)(mt * 16 + lrow) * 264 + colb + lcol);
#pragma unroll
                for (int mt = 0; mt < 4; mt++)
#pragma unroll
                    for (int nt = 0; nt < 4; nt++)
                        mma16816(acc[mt][nt], a[mt], bfrag[kc][kk2][nt]);
            }
        }

        // partial store: warp-exclusive padded region (no pre-sync needed)
        float* pw = part + w * 2304;
#pragma unroll
        for (int mt = 0; mt < 4; mt++)
#pragma unroll
            for (int nt = 0; nt < 4; nt++) {
                const int r = mt * 16 + g, c = nt * 8 + tg * 2;
                *(float2*)&pw[r * 36 + c]       = make_float2(acc[mt][nt][0], acc[mt][nt][1]);
                *(float2*)&pw[(r + 8) * 36 + c] = make_float2(acc[mt][nt][2], acc[mt][nt][3]);
            }
        __syncthreads();

        // fused reduce + gates + state update (pairs tid and tid+256)
        {
            float4 bb = *(const float4*)(bias + hu0 * 4);
            float xf = pr0.x + bb.x, xi = pr0.y + bb.y, xg = pr0.z + bb.z, xo = pr0.w + bb.w;
#pragma unroll
            for (int ww = 0; ww < 8; ++ww) {
                float4 q = *(const float4*)(part + ww * 2304 + b0 * 36 + hu0 * 4);
                xf += q.x; xi += q.y; xg += q.z; xo += q.w;
            }
            float f = sigf(xf), ii = sigf(xi), gg = tanhx(xg), o = sigf(xo);
            cst0 = cst0 * f + gg * ii;
            hdst[b0 * HIDDEN + cta * 8 + hu0] = __float2half(cst0 * o);
        }
        {
            float4 bb = *(const float4*)(bias + hu1 * 4);
            float xf = pr1.x + bb.x, xi = pr1.y + bb.y, xg = pr1.z + bb.z, xo = pr1.w + bb.w;
#pragma unroll
            for (int ww = 0; ww < 8; ++ww) {
                float4 q = *(const float4*)(part + ww * 2304 + b1 * 36 + hu1 * 4);
                xf += q.x; xi += q.y; xg += q.z; xo += q.w;
            }
            float f = sigf(xf), ii = sigf(xi), gg = tanhx(xg), o = sigf(xo);
            cst1 = cst1 * f + gg * ii;
            hdst[b1 * HIDDEN + cta * 8 + hu1] = __float2half(cst1 * o);
        }

        // grid barrier (proven: atomic + single spinner per CTA)
        __threadfence();
        __syncthreads();
        if (tid == 0) {
            atomicAdd(&g_bar, 1u);
            unsigned target = (unsigned)(t + 1) * gridDim.x;
            while (*(volatile unsigned*)&g_bar < target) { }
        }
        __syncthreads();
    }
}

// ---------------- readout: logits = h_final @ Wout + bout ----------------
__global__ void __launch_bounds__(256, 1) k_readout(const float* __restrict__ bout,
                                                    float* __restrict__ out) {
    extern __shared__ char smem[];
    __half* hsm   = (__half*)smem;                  // [64][1032]  132096 B
    float*  stage = (float*)(smem + 132096);        // [64][132]   33792 B
    const int n0 = blockIdx.x * 128;
    const int tid = threadIdx.x;
    const int w = tid >> 5;
    const __half* hfin = g_h[0];   // final h after SEQ=512 steps

    for (int i = tid; i < 64 * 128; i += 256) {
        int r = i >> 7, c = i & 127;
        *(float4*)(hsm + r * 1032 + c * 8) = *(const float4*)(hfin + (size_t)r * HIDDEN + c * 8);
    }
    __syncthreads();

    wmma::fragment<wmma::accumulator, 16, 16, 16, float> acc[4];
#pragma unroll
    for (int i = 0; i < 4; i++) wmma::fill_fragment(acc[i], 0.f);

#pragma unroll 1
    for (int kk = 0; kk < 64; ++kk) {
        wmma::fragment<wmma::matrix_a, 16, 16, 16, __half, wmma::row_major> fa;
        wmma::fragment<wmma::matrix_b, 16, 16, 16, __half, wmma::row_major> fb;
        wmma::load_matrix_sync(fb, g_wout + (size_t)(kk * 16) * VOCAB + n0 + w * 16, VOCAB);
#pragma unroll
        for (int i = 0; i < 4; i++) {
            wmma::load_matrix_sync(fa, hsm + i * 16 * 1032 + kk * 16, 1032);
            wmma::mma_sync(acc[i], fa, fb, acc[i]);
        }
    }
#pragma unroll
    for (int i = 0; i < 4; i++)
        wmma::store_matrix_sync(stage + i * 16 * 132 + w * 16, acc[i], 132, wmma::mem_row_major);
    __syncthreads();

    for (int i = tid; i < 64 * 128; i += 256) {
        int r = i >> 7, c = i & 127;
        out[(size_t)r * VOCAB + n0 + c] = stage[r * 132 + c] + bout[n0 + c];
    }
}

// ---------------- launch ----------------
extern "C" void kernel_launch(void* const* d_in, const int* in_sizes, int n_in,
                              void* d_out, int out_size) {
    const int*   ids  = (const int*)d_in[0];
    const float* emb  = (const float*)d_in[1];
    const float* Wf   = (const float*)d_in[2];
    const float* bf   = (const float*)d_in[3];
    const float* Wi   = (const float*)d_in[4];
    const float* bi   = (const float*)d_in[5];
    const float* Wc   = (const float*)d_in[6];
    const float* bc   = (const float*)d_in[7];
    const float* Wo   = (const float*)d_in[8];
    const float* bo   = (const float*)d_in[9];
    const float* Wout = (const float*)d_in[10];
    const float* bout = (const float*)d_in[11];
    float* out = (float*)d_out;

    const int smem1 = 36864 + 34816;                                  // 71680
    const int smemR = 101376 + 73728 + 128;                           // 175232
    const int smemO = 64 * 1032 * 2 + 64 * 132 * 4;                   // 165888
    cudaFuncSetAttribute(k_gemm1,   cudaFuncAttributeMaxDynamicSharedMemorySize, smem1);
    cudaFuncSetAttribute(k_rnn,     cudaFuncAttributeMaxDynamicSharedMemorySize, smemR);
    cudaFuncSetAttribute(k_readout, cudaFuncAttributeMaxDynamicSharedMemorySize, smemO);

    k_init<<<256, 256>>>();
    k_convw<<<(1536 * 1024 + 255) / 256, 256>>>(Wf, Wi, Wc, Wo, bf, bi, bc, bo);
    k_convwout<<<8192, 256>>>(Wout);
    k_gather<<<NTOK * (EMBED / 8) / 256, 256>>>(ids, emb);
    k_gemm1<<<dim3(DGATE / 128, NTOK / 128), 256, smem1>>>();
    k_rnn<<<128, 256, smemR>>>();
    k_readout<<<VOCAB / 128, 256, smemO>>>(bout, out);
}